// round 6
// baseline (speedup 1.0000x reference)
#include <cuda_runtime.h>
#include <math.h>

#define T_STEPS 1000
#define BATCH   1024
#define IN_DIM  80
#define HID     128
#define OUT_DIM 10

#define CHUNKS   8
#define CH_STEPS (T_STEPS / CHUNKS)                 // 125
#define TILES_PER_CHUNK (CH_STEPS * BATCH / 128)    // 1000

__device__ float g_xw[(size_t)T_STEPS * BATCH * HID];   // 524 MB (BSS)
__device__ float g_coef[T_STEPS];
__device__ float g_wrp[HID * HID];     // R2-layout permuted w_rec^T
__device__ float g_v[BATCH * HID];     // carried LIF state between chunks
__device__ float g_i[BATCH * HID];
__device__ float g_a[BATCH * HID];     // folded readout accumulator

// ---------------------------------------------------------------------------
// Prep: coefficients (closed form c_u = 0.9^(T-u) - 0.8^(T-u)) and permuted
// recurrent weights: g_wrp[k*128 + ln*4 + r] = wrec[(r*32+ln)*128 + k]
// (one conflict-free float4 per spiking column in the sim).
// ---------------------------------------------------------------------------
__global__ void prep_kernel(const float* __restrict__ wrec) {
    int idx = blockIdx.x * blockDim.x + threadIdx.x;
    if (idx < HID * HID) {
        int k = idx >> 7, j = idx & 127;
        int ln = j >> 2, r = j & 3;
        g_wrp[idx] = wrec[(r * 32 + ln) * HID + k];
    }
    if (idx < T_STEPS) {
        double n = (double)(T_STEPS - idx);
        g_coef[idx] = (float)(pow(0.9, n) - pow(0.8, n));
    }
}

// ---------------------------------------------------------------------------
// Input GEMM chunk: rows [tile0*128, ...) of (T*B,80)@(80,128) -> g_xw.
// Scalar FFMA, per-element serial ascending-k chain (bitwise == R2 gemm).
// SMEM trimmed to 81,920 B for co-residency with the sim kernel:
//   xs  [128][80]  — microtile 'a' reads are half-warp broadcasts (conflict-
//                    immune, no padding needed)
//   wsT [80][128]  — transposed, 16 distinct banks + 2-way broadcast per read
// ---------------------------------------------------------------------------
#define GEMM_SMEM ((128 * IN_DIM + IN_DIM * HID) * 4)   // 81,920 B

__global__ __launch_bounds__(256, 2)
void gemm_in(const float* __restrict__ x, const float* __restrict__ w,
             int tile0) {
    extern __shared__ float sm[];
    float* xs  = sm;                  // [128][IN_DIM]
    float* wsT = sm + 128 * IN_DIM;   // [IN_DIM][HID]
    int tid = threadIdx.x;
    size_t rowbase = (size_t)(tile0 + blockIdx.x) * 128;

    const float4* xg = (const float4*)(x + rowbase * IN_DIM);
#pragma unroll
    for (int it = 0; it < 10; ++it) {
        int e = tid + it * 256;
        int row = e / 20, c4 = e % 20;
        float4 v = xg[e];
        *(float4*)&xs[row * IN_DIM + c4 * 4] = v;
    }
    // wsT[k*128 + h] = w[h*80 + k]; consecutive e -> conflict-free smem stores
    for (int e = tid; e < IN_DIM * HID; e += 256) {
        int k = e >> 7, h = e & 127;
        wsT[e] = w[h * IN_DIM + k];
    }
    __syncthreads();

    int mrow = (tid >> 4) * 8;
    int mcol = tid & 15;
    float acc[8][8];
#pragma unroll
    for (int i = 0; i < 8; i++)
#pragma unroll
        for (int j = 0; j < 8; j++) acc[i][j] = 0.f;

#pragma unroll 4
    for (int k = 0; k < IN_DIM; ++k) {
        float a[8], bb[8];
#pragma unroll
        for (int i = 0; i < 8; i++) a[i] = xs[(mrow + i) * IN_DIM + k];
#pragma unroll
        for (int j = 0; j < 8; j++) bb[j] = wsT[k * HID + mcol + 16 * j];
#pragma unroll
        for (int i = 0; i < 8; i++)
#pragma unroll
            for (int j = 0; j < 8; j++)
                acc[i][j] = fmaf(a[i], bb[j], acc[i][j]);
    }

    float* op = g_xw + rowbase * HID;
#pragma unroll
    for (int i = 0; i < 8; i++)
#pragma unroll
        for (int j = 0; j < 8; j++)
            op[(mrow + i) * HID + mcol + 16 * j] = acc[i][j];
}

// ---------------------------------------------------------------------------
// Simulation chunk [t0, t0+CH_STEPS): R2's exact numeric path (1 warp per
// batch element, h = r*32+lane, ballot drain ascending-k, separate-R
// association). State round-trips through gmem in exact fp32 bits.
// SMEM = w_rec only (65,536 B); cf and w_out read from gmem (L1-hot).
// ---------------------------------------------------------------------------
#define SIM_SMEM (HID * HID * 4)   // 65,536 B

__global__ __launch_bounds__(256)
void sim_kernel(const float* __restrict__ wout, float* __restrict__ out,
                int t0) {
    extern __shared__ float sm[];
    float* wrp = sm;
    int tid = threadIdx.x, lane = tid & 31, wid = tid >> 5;
    int b = blockIdx.x * 8 + wid;

    {
        const float4* s4 = (const float4*)g_wrp;
        float4* d4 = (float4*)wrp;
        for (int e = tid; e < HID * HID / 4; e += 256) d4[e] = s4[e];
    }
    __syncthreads();

    float v0, v1, v2, v3, i0, i1, i2, i3, a0, a1, a2, a3;
    if (t0 == 0) {
        v0 = v1 = v2 = v3 = 0.f;
        i0 = i1 = i2 = i3 = 0.f;
        a0 = a1 = a2 = a3 = 0.f;
    } else {
        const float* pv = g_v + b * HID;
        const float* pi = g_i + b * HID;
        const float* pa = g_a + b * HID;
        v0 = pv[lane]; v1 = pv[32 + lane]; v2 = pv[64 + lane]; v3 = pv[96 + lane];
        i0 = pi[lane]; i1 = pi[32 + lane]; i2 = pi[64 + lane]; i3 = pi[96 + lane];
        a0 = pa[lane]; a1 = pa[32 + lane]; a2 = pa[64 + lane]; a3 = pa[96 + lane];
    }

    const float* xwp = g_xw + ((size_t)t0 * BATCH + b) * HID + lane;
    const size_t tstride = (size_t)BATCH * HID;
    const float4* wr4 = (const float4*)wrp;   // column k: wr4[k*32 + lane]

    float xn0 = xwp[0], xn1 = xwp[32], xn2 = xwp[64], xn3 = xwp[96];

    for (int tl = 0; tl < CH_STEPS; ++tl) {
        float xc0 = xn0, xc1 = xn1, xc2 = xn2, xc3 = xn3;
        if (tl + 1 < CH_STEPS) {
            const float* p = xwp + (size_t)(tl + 1) * tstride;
            xn0 = p[0]; xn1 = p[32]; xn2 = p[64]; xn3 = p[96];
        }
        float ct = __ldg(&g_coef[t0 + tl]);

        float vd0 = __fadd_rn(v0, __fmul_rn(0.1f, __fadd_rn(__fsub_rn(0.f, v0), i0)));
        float vd1 = __fadd_rn(v1, __fmul_rn(0.1f, __fadd_rn(__fsub_rn(0.f, v1), i1)));
        float vd2 = __fadd_rn(v2, __fmul_rn(0.1f, __fadd_rn(__fsub_rn(0.f, v2), i2)));
        float vd3 = __fadd_rn(v3, __fmul_rn(0.1f, __fadd_rn(__fsub_rn(0.f, v3), i3)));
        float id0 = __fsub_rn(i0, __fmul_rn(0.2f, i0));
        float id1 = __fsub_rn(i1, __fmul_rn(0.2f, i1));
        float id2 = __fsub_rn(i2, __fmul_rn(0.2f, i2));
        float id3 = __fsub_rn(i3, __fmul_rn(0.2f, i3));
        bool z0 = __fsub_rn(vd0, 1.0f) > 0.0f;
        bool z1 = __fsub_rn(vd1, 1.0f) > 0.0f;
        bool z2 = __fsub_rn(vd2, 1.0f) > 0.0f;
        bool z3 = __fsub_rn(vd3, 1.0f) > 0.0f;
        v0 = z0 ? 0.0f : vd0;
        v1 = z1 ? 0.0f : vd1;
        v2 = z2 ? 0.0f : vd2;
        v3 = z3 ? 0.0f : vd3;
        if (z0) a0 = __fadd_rn(a0, ct);
        if (z1) a1 = __fadd_rn(a1, ct);
        if (z2) a2 = __fadd_rn(a2, ct);
        if (z3) a3 = __fadd_rn(a3, ct);

        unsigned m0 = __ballot_sync(0xffffffffu, z0);
        unsigned m1 = __ballot_sync(0xffffffffu, z1);
        unsigned m2 = __ballot_sync(0xffffffffu, z2);
        unsigned m3 = __ballot_sync(0xffffffffu, z3);
        float R0 = 0.f, R1 = 0.f, R2 = 0.f, R3 = 0.f;
        while (m0) {
            int k = __ffs((int)m0) - 1; m0 &= m0 - 1;
            float4 q = wr4[k * 32 + lane];
            R0 = __fadd_rn(R0, q.x); R1 = __fadd_rn(R1, q.y);
            R2 = __fadd_rn(R2, q.z); R3 = __fadd_rn(R3, q.w);
        }
        while (m1) {
            int k = 32 + __ffs((int)m1) - 1; m1 &= m1 - 1;
            float4 q = wr4[k * 32 + lane];
            R0 = __fadd_rn(R0, q.x); R1 = __fadd_rn(R1, q.y);
            R2 = __fadd_rn(R2, q.z); R3 = __fadd_rn(R3, q.w);
        }
        while (m2) {
            int k = 64 + __ffs((int)m2) - 1; m2 &= m2 - 1;
            float4 q = wr4[k * 32 + lane];
            R0 = __fadd_rn(R0, q.x); R1 = __fadd_rn(R1, q.y);
            R2 = __fadd_rn(R2, q.z); R3 = __fadd_rn(R3, q.w);
        }
        while (m3) {
            int k = 96 + __ffs((int)m3) - 1; m3 &= m3 - 1;
            float4 q = wr4[k * 32 + lane];
            R0 = __fadd_rn(R0, q.x); R1 = __fadd_rn(R1, q.y);
            R2 = __fadd_rn(R2, q.z); R3 = __fadd_rn(R3, q.w);
        }
        i0 = __fadd_rn(__fadd_rn(id0, xc0), R0);
        i1 = __fadd_rn(__fadd_rn(id1, xc1), R1);
        i2 = __fadd_rn(__fadd_rn(id2, xc2), R2);
        i3 = __fadd_rn(__fadd_rn(id3, xc3), R3);
    }

    if (t0 + CH_STEPS < T_STEPS) {
        float* pv = g_v + b * HID;
        float* pi = g_i + b * HID;
        float* pa = g_a + b * HID;
        pv[lane] = v0; pv[32 + lane] = v1; pv[64 + lane] = v2; pv[96 + lane] = v3;
        pi[lane] = i0; pi[32 + lane] = i1; pi[64 + lane] = i2; pi[96 + lane] = i3;
        pa[lane] = a0; pa[32 + lane] = a1; pa[64 + lane] = a2; pa[96 + lane] = a3;
    } else {
        // Final readout: vo[o] = sum_h acc[h]*w_out[o][h]; h = r*32+lane
        float vo[OUT_DIM];
#pragma unroll
        for (int o = 0; o < OUT_DIM; ++o) {
            const float* wp = wout + o * HID;
            float p = a0 * wp[lane] + a1 * wp[32 + lane] + a2 * wp[64 + lane] +
                      a3 * wp[96 + lane];
#pragma unroll
            for (int s = 16; s; s >>= 1) p += __shfl_xor_sync(0xffffffffu, p, s);
            vo[o] = p;
        }
        if (lane == 0) {
            float mx = vo[0];
#pragma unroll
            for (int o = 1; o < OUT_DIM; ++o) mx = fmaxf(mx, vo[o]);
            float se = 0.f;
#pragma unroll
            for (int o = 0; o < OUT_DIM; ++o) se += expf(vo[o] - mx);
            float lse = mx + logf(se);
#pragma unroll
            for (int o = 0; o < OUT_DIM; ++o) out[b * OUT_DIM + o] = vo[o] - lse;
        }
    }
}

extern "C" void kernel_launch(void* const* d_in, const int* in_sizes, int n_in,
                              void* d_out, int out_size) {
    const float* x     = (const float*)d_in[0];
    const float* w_in  = (const float*)d_in[1];
    const float* w_rec = (const float*)d_in[2];
    const float* w_out = (const float*)d_in[3];
    float* out = (float*)d_out;

    cudaFuncSetAttribute(gemm_in, cudaFuncAttributeMaxDynamicSharedMemorySize,
                         GEMM_SMEM);
    cudaFuncSetAttribute(sim_kernel, cudaFuncAttributeMaxDynamicSharedMemorySize,
                         SIM_SMEM);

    // Fork a non-blocking stream for the GEMM pipeline (created fresh per
    // call; host-side objects only, no device allocation).
    cudaStream_t s1;
    cudaStreamCreateWithFlags(&s1, cudaStreamNonBlocking);
    cudaEvent_t evF;
    cudaEventCreateWithFlags(&evF, cudaEventDisableTiming);
    cudaEvent_t evg[CHUNKS];
    for (int c = 0; c < CHUNKS; ++c)
        cudaEventCreateWithFlags(&evg[c], cudaEventDisableTiming);

    // Fork point: gemm chunks are independent of prep.
    cudaEventRecord(evF, 0);
    cudaStreamWaitEvent(s1, evF, 0);

    prep_kernel<<<64, 256, 0, 0>>>(w_rec);   // stream 0: before all sim chunks

    for (int c = 0; c < CHUNKS; ++c) {
        gemm_in<<<TILES_PER_CHUNK, 256, GEMM_SMEM, s1>>>(
            x, w_in, c * TILES_PER_CHUNK);
        cudaEventRecord(evg[c], s1);
    }
    for (int c = 0; c < CHUNKS; ++c) {
        cudaStreamWaitEvent(0, evg[c], 0);
        sim_kernel<<<BATCH / 8, 256, SIM_SMEM, 0>>>(w_out, out, c * CH_STEPS);
    }
}

// round 8
// speedup vs baseline: 1.0025x; 1.0025x over previous
#include <cuda_runtime.h>
#include <math.h>

#define T_STEPS 1000
#define BATCH   1024
#define IN_DIM  80
#define HID     128
#define OUT_DIM 10

#define CHUNKS   8
#define CH_STEPS (T_STEPS / CHUNKS)                 // 125
#define TILES_PER_CHUNK (CH_STEPS * BATCH / 128)    // 1000

__device__ float g_xw[(size_t)T_STEPS * BATCH * HID];   // 524 MB (BSS)
__device__ float g_coef[T_STEPS];
__device__ float g_wrp[HID * HID];     // R2-layout permuted w_rec^T
__device__ float g_v[BATCH * HID];     // carried LIF state between chunks
__device__ float g_i[BATCH * HID];
__device__ float g_a[BATCH * HID];     // folded readout accumulator

// ---------------------------------------------------------------------------
// Prep: coefficients (closed form c_u = 0.9^(T-u) - 0.8^(T-u)) and permuted
// recurrent weights: g_wrp[k*128 + ln*4 + r] = wrec[(r*32+ln)*128 + k].
// ---------------------------------------------------------------------------
__global__ void prep_kernel(const float* __restrict__ wrec) {
    int idx = blockIdx.x * blockDim.x + threadIdx.x;
    if (idx < HID * HID) {
        int k = idx >> 7, j = idx & 127;
        int ln = j >> 2, r = j & 3;
        g_wrp[idx] = wrec[(r * 32 + ln) * HID + k];
    }
    if (idx < T_STEPS) {
        double n = (double)(T_STEPS - idx);
        g_coef[idx] = (float)(pow(0.9, n) - pow(0.8, n));
    }
}

// ---------------------------------------------------------------------------
// Input GEMM chunk: rows of (T*B,80)@(80,128) -> g_xw. Scalar FFMA chain,
// per-element ascending-k (bitwise == R2). LDS minimized: both operand
// fetches are LDS.128 over k-quads (stride 84 words -> conflict-free).
// Dynamic smem padded to 116 KB to cap residency at 1 CTA/SM so a 64 KB sim
// CTA co-resides (116+64=180 <= 228 KB carveout).
// ---------------------------------------------------------------------------
#define XS_STR 84   // %4==0 for LDS.128; row-pad avoids conflicts
#define WS_STR 84
#define GEMM_SMEM_USED ((128 * XS_STR + 128 * WS_STR) * 4)   // 86,016 B
#define GEMM_SMEM (116 * 1024)                                // occupancy cap

__global__ __launch_bounds__(256, 1)
void gemm_in(const float* __restrict__ x, const float* __restrict__ w,
             int tile0) {
    extern __shared__ float sm[];
    float* xs = sm;                 // [128][XS_STR]
    float* ws = sm + 128 * XS_STR;  // [128][WS_STR]
    int tid = threadIdx.x;
    size_t rowbase = (size_t)(tile0 + blockIdx.x) * 128;

    const float4* xg = (const float4*)(x + rowbase * IN_DIM);
#pragma unroll
    for (int it = 0; it < 10; ++it) {
        int e = tid + it * 256;
        int row = e / 20, c4 = e % 20;
        float4 v = xg[e];
        *(float4*)&xs[row * XS_STR + c4 * 4] = v;
    }
    for (int e = tid; e < HID * IN_DIM; e += 256)
        ws[(e / IN_DIM) * WS_STR + (e % IN_DIM)] = w[e];
    __syncthreads();

    int mrow = (tid >> 4) * 8;
    int mcol = tid & 15;
    float acc[8][8];
#pragma unroll
    for (int i = 0; i < 8; i++)
#pragma unroll
        for (int j = 0; j < 8; j++) acc[i][j] = 0.f;

#pragma unroll 2
    for (int k = 0; k < IN_DIM; k += 4) {
        float4 a4[8], b4[8];
#pragma unroll
        for (int i = 0; i < 8; i++)
            a4[i] = *(const float4*)&xs[(mrow + i) * XS_STR + k];
#pragma unroll
        for (int j = 0; j < 8; j++)
            b4[j] = *(const float4*)&ws[(mcol + 16 * j) * WS_STR + k];
        // ascending-k chain per element: k, k+1, k+2, k+3
#pragma unroll
        for (int i = 0; i < 8; i++)
#pragma unroll
            for (int j = 0; j < 8; j++) {
                acc[i][j] = fmaf(a4[i].x, b4[j].x, acc[i][j]);
                acc[i][j] = fmaf(a4[i].y, b4[j].y, acc[i][j]);
                acc[i][j] = fmaf(a4[i].z, b4[j].z, acc[i][j]);
                acc[i][j] = fmaf(a4[i].w, b4[j].w, acc[i][j]);
            }
    }

    float* op = g_xw + rowbase * HID;
#pragma unroll
    for (int i = 0; i < 8; i++)
#pragma unroll
        for (int j = 0; j < 8; j++)
            op[(mrow + i) * HID + mcol + 16 * j] = acc[i][j];
}

// ---------------------------------------------------------------------------
// Simulation chunk [t0, t0+CH_STEPS): R2's exact numeric path. State
// round-trips through gmem in exact fp32 bits. SMEM = w_rec only (64 KB).
// ---------------------------------------------------------------------------
#define SIM_SMEM (HID * HID * 4)   // 65,536 B

__global__ __launch_bounds__(256)
void sim_kernel(const float* __restrict__ wout, float* __restrict__ out,
                int t0) {
    extern __shared__ float sm[];
    float* wrp = sm;
    int tid = threadIdx.x, lane = tid & 31, wid = tid >> 5;
    int b = blockIdx.x * 8 + wid;

    {
        const float4* s4 = (const float4*)g_wrp;
        float4* d4 = (float4*)wrp;
        for (int e = tid; e < HID * HID / 4; e += 256) d4[e] = s4[e];
    }
    __syncthreads();

    float v0, v1, v2, v3, i0, i1, i2, i3, a0, a1, a2, a3;
    if (t0 == 0) {
        v0 = v1 = v2 = v3 = 0.f;
        i0 = i1 = i2 = i3 = 0.f;
        a0 = a1 = a2 = a3 = 0.f;
    } else {
        const float* pv = g_v + b * HID;
        const float* pi = g_i + b * HID;
        const float* pa = g_a + b * HID;
        v0 = pv[lane]; v1 = pv[32 + lane]; v2 = pv[64 + lane]; v3 = pv[96 + lane];
        i0 = pi[lane]; i1 = pi[32 + lane]; i2 = pi[64 + lane]; i3 = pi[96 + lane];
        a0 = pa[lane]; a1 = pa[32 + lane]; a2 = pa[64 + lane]; a3 = pa[96 + lane];
    }

    const float* xwp = g_xw + ((size_t)t0 * BATCH + b) * HID + lane;
    const size_t tstride = (size_t)BATCH * HID;
    const float4* wr4 = (const float4*)wrp;

    float xn0 = xwp[0], xn1 = xwp[32], xn2 = xwp[64], xn3 = xwp[96];

    for (int tl = 0; tl < CH_STEPS; ++tl) {
        float xc0 = xn0, xc1 = xn1, xc2 = xn2, xc3 = xn3;
        if (tl + 1 < CH_STEPS) {
            const float* p = xwp + (size_t)(tl + 1) * tstride;
            xn0 = p[0]; xn1 = p[32]; xn2 = p[64]; xn3 = p[96];
        }
        float ct = __ldg(&g_coef[t0 + tl]);

        float vd0 = __fadd_rn(v0, __fmul_rn(0.1f, __fadd_rn(__fsub_rn(0.f, v0), i0)));
        float vd1 = __fadd_rn(v1, __fmul_rn(0.1f, __fadd_rn(__fsub_rn(0.f, v1), i1)));
        float vd2 = __fadd_rn(v2, __fmul_rn(0.1f, __fadd_rn(__fsub_rn(0.f, v2), i2)));
        float vd3 = __fadd_rn(v3, __fmul_rn(0.1f, __fadd_rn(__fsub_rn(0.f, v3), i3)));
        float id0 = __fsub_rn(i0, __fmul_rn(0.2f, i0));
        float id1 = __fsub_rn(i1, __fmul_rn(0.2f, i1));
        float id2 = __fsub_rn(i2, __fmul_rn(0.2f, i2));
        float id3 = __fsub_rn(i3, __fmul_rn(0.2f, i3));
        bool z0 = __fsub_rn(vd0, 1.0f) > 0.0f;
        bool z1 = __fsub_rn(vd1, 1.0f) > 0.0f;
        bool z2 = __fsub_rn(vd2, 1.0f) > 0.0f;
        bool z3 = __fsub_rn(vd3, 1.0f) > 0.0f;
        v0 = z0 ? 0.0f : vd0;
        v1 = z1 ? 0.0f : vd1;
        v2 = z2 ? 0.0f : vd2;
        v3 = z3 ? 0.0f : vd3;
        if (z0) a0 = __fadd_rn(a0, ct);
        if (z1) a1 = __fadd_rn(a1, ct);
        if (z2) a2 = __fadd_rn(a2, ct);
        if (z3) a3 = __fadd_rn(a3, ct);

        unsigned m0 = __ballot_sync(0xffffffffu, z0);
        unsigned m1 = __ballot_sync(0xffffffffu, z1);
        unsigned m2 = __ballot_sync(0xffffffffu, z2);
        unsigned m3 = __ballot_sync(0xffffffffu, z3);
        float R0 = 0.f, R1 = 0.f, R2 = 0.f, R3 = 0.f;
        while (m0) {
            int k = __ffs((int)m0) - 1; m0 &= m0 - 1;
            float4 q = wr4[k * 32 + lane];
            R0 = __fadd_rn(R0, q.x); R1 = __fadd_rn(R1, q.y);
            R2 = __fadd_rn(R2, q.z); R3 = __fadd_rn(R3, q.w);
        }
        while (m1) {
            int k = 32 + __ffs((int)m1) - 1; m1 &= m1 - 1;
            float4 q = wr4[k * 32 + lane];
            R0 = __fadd_rn(R0, q.x); R1 = __fadd_rn(R1, q.y);
            R2 = __fadd_rn(R2, q.z); R3 = __fadd_rn(R3, q.w);
        }
        while (m2) {
            int k = 64 + __ffs((int)m2) - 1; m2 &= m2 - 1;
            float4 q = wr4[k * 32 + lane];
            R0 = __fadd_rn(R0, q.x); R1 = __fadd_rn(R1, q.y);
            R2 = __fadd_rn(R2, q.z); R3 = __fadd_rn(R3, q.w);
        }
        while (m3) {
            int k = 96 + __ffs((int)m3) - 1; m3 &= m3 - 1;
            float4 q = wr4[k * 32 + lane];
            R0 = __fadd_rn(R0, q.x); R1 = __fadd_rn(R1, q.y);
            R2 = __fadd_rn(R2, q.z); R3 = __fadd_rn(R3, q.w);
        }
        i0 = __fadd_rn(__fadd_rn(id0, xc0), R0);
        i1 = __fadd_rn(__fadd_rn(id1, xc1), R1);
        i2 = __fadd_rn(__fadd_rn(id2, xc2), R2);
        i3 = __fadd_rn(__fadd_rn(id3, xc3), R3);
    }

    if (t0 + CH_STEPS < T_STEPS) {
        float* pv = g_v + b * HID;
        float* pi = g_i + b * HID;
        float* pa = g_a + b * HID;
        pv[lane] = v0; pv[32 + lane] = v1; pv[64 + lane] = v2; pv[96 + lane] = v3;
        pi[lane] = i0; pi[32 + lane] = i1; pi[64 + lane] = i2; pi[96 + lane] = i3;
        pa[lane] = a0; pa[32 + lane] = a1; pa[64 + lane] = a2; pa[96 + lane] = a3;
    } else {
        float vo[OUT_DIM];
#pragma unroll
        for (int o = 0; o < OUT_DIM; ++o) {
            const float* wp = wout + o * HID;
            float p = a0 * wp[lane] + a1 * wp[32 + lane] + a2 * wp[64 + lane] +
                      a3 * wp[96 + lane];
#pragma unroll
            for (int s = 16; s; s >>= 1) p += __shfl_xor_sync(0xffffffffu, p, s);
            vo[o] = p;
        }
        if (lane == 0) {
            float mx = vo[0];
#pragma unroll
            for (int o = 1; o < OUT_DIM; ++o) mx = fmaxf(mx, vo[o]);
            float se = 0.f;
#pragma unroll
            for (int o = 0; o < OUT_DIM; ++o) se += expf(vo[o] - mx);
            float lse = mx + logf(se);
#pragma unroll
            for (int o = 0; o < OUT_DIM; ++o) out[b * OUT_DIM + o] = vo[o] - lse;
        }
    }
}

extern "C" void kernel_launch(void* const* d_in, const int* in_sizes, int n_in,
                              void* d_out, int out_size) {
    const float* x     = (const float*)d_in[0];
    const float* w_in  = (const float*)d_in[1];
    const float* w_rec = (const float*)d_in[2];
    const float* w_out = (const float*)d_in[3];
    float* out = (float*)d_out;

    cudaFuncSetAttribute(gemm_in, cudaFuncAttributeMaxDynamicSharedMemorySize,
                         GEMM_SMEM);
    cudaFuncSetAttribute(sim_kernel, cudaFuncAttributeMaxDynamicSharedMemorySize,
                         SIM_SMEM);

    // GEMM pipeline on a low-priority forked stream; sim chunks on stream 0.
    int prLo = 0, prHi = 0;
    cudaDeviceGetStreamPriorityRange(&prLo, &prHi);
    cudaStream_t s1;
    cudaStreamCreateWithPriority(&s1, cudaStreamNonBlocking, prLo);
    cudaEvent_t evF;
    cudaEventCreateWithFlags(&evF, cudaEventDisableTiming);
    cudaEvent_t evg[CHUNKS];
    for (int c = 0; c < CHUNKS; ++c)
        cudaEventCreateWithFlags(&evg[c], cudaEventDisableTiming);

    cudaEventRecord(evF, 0);
    cudaStreamWaitEvent(s1, evF, 0);

    prep_kernel<<<64, 256, 0, 0>>>(w_rec);

    for (int c = 0; c < CHUNKS; ++c) {
        gemm_in<<<TILES_PER_CHUNK, 256, GEMM_SMEM, s1>>>(
            x, w_in, c * TILES_PER_CHUNK);
        cudaEventRecord(evg[c], s1);
    }
    for (int c = 0; c < CHUNKS; ++c) {
        cudaStreamWaitEvent(0, evg[c], 0);
        sim_kernel<<<BATCH / 8, 256, SIM_SMEM, 0>>>(w_out, out, c * CH_STEPS);
    }
}

// round 9
// speedup vs baseline: 1.0169x; 1.0144x over previous
#include <cuda_runtime.h>
#include <math.h>

#define T_STEPS 1000
#define BATCH   1024
#define IN_DIM  80
#define HID     128
#define OUT_DIM 10

#define CHUNKS   8
#define CH_STEPS (T_STEPS / CHUNKS)                 // 125
#define TILES_PER_CHUNK (CH_STEPS * BATCH / 128)    // 1000

__device__ float g_xw[(size_t)T_STEPS * BATCH * HID];   // 524 MB (BSS)
__device__ float g_coef[T_STEPS];
__device__ float g_wrp[HID * HID];     // R2-layout permuted w_rec^T
__device__ float g_v[BATCH * HID];     // carried LIF state between chunks
__device__ float g_i[BATCH * HID];
__device__ float g_a[BATCH * HID];     // folded readout accumulator

// ---------------------------------------------------------------------------
// Prep: coefficients (closed form c_u = 0.9^(T-u) - 0.8^(T-u)) and permuted
// recurrent weights: g_wrp[k*128 + ln*4 + r] = wrec[(r*32+ln)*128 + k].
// ---------------------------------------------------------------------------
__global__ void prep_kernel(const float* __restrict__ wrec) {
    int idx = blockIdx.x * blockDim.x + threadIdx.x;
    if (idx < HID * HID) {
        int k = idx >> 7, j = idx & 127;
        int ln = j >> 2, r = j & 3;
        g_wrp[idx] = wrec[(r * 32 + ln) * HID + k];
    }
    if (idx < T_STEPS) {
        double n = (double)(T_STEPS - idx);
        g_coef[idx] = (float)(pow(0.9, n) - pow(0.8, n));
    }
}

// ---------------------------------------------------------------------------
// Input GEMM chunk: rows of (T*B,80)@(80,128) -> g_xw. Scalar FFMA chain,
// per-element ascending-k (bitwise == R2/R8; rel_err must stay 6.043687e-4).
// REG-CAPPED to 128 (launch_bounds minBlocks=2) so a sim CTA can co-reside:
//   gemm 128r*256t = 32768 + sim ~100r*256t = 25600  ->  58.4K <= 64K RF.
// Live set kept small: a4[8] quad-buffered, b4 loaded per-j and consumed.
// SMEM padded to 116 KB -> exactly 1 gemm CTA/SM; 116+64(sim) <= 228 KB.
// ---------------------------------------------------------------------------
#define XS_STR 84   // %4==0 for LDS.128
#define WS_STR 84
#define GEMM_SMEM (116 * 1024)

__global__ __launch_bounds__(256, 2)   // minBlocks=2 acts as a 128-reg cap
void gemm_in(const float* __restrict__ x, const float* __restrict__ w,
             int tile0) {
    extern __shared__ float sm[];
    float* xs = sm;                 // [128][XS_STR]
    float* ws = sm + 128 * XS_STR;  // [128][WS_STR]
    int tid = threadIdx.x;
    size_t rowbase = (size_t)(tile0 + blockIdx.x) * 128;

    const float4* xg = (const float4*)(x + rowbase * IN_DIM);
#pragma unroll
    for (int it = 0; it < 10; ++it) {
        int e = tid + it * 256;
        int row = e / 20, c4 = e % 20;
        float4 v = xg[e];
        *(float4*)&xs[row * XS_STR + c4 * 4] = v;
    }
    for (int e = tid; e < HID * IN_DIM; e += 256)
        ws[(e / IN_DIM) * WS_STR + (e % IN_DIM)] = w[e];
    __syncthreads();

    int mrow = (tid >> 4) * 8;
    int mcol = tid & 15;
    float acc[8][8];
#pragma unroll
    for (int i = 0; i < 8; i++)
#pragma unroll
        for (int j = 0; j < 8; j++) acc[i][j] = 0.f;

    for (int k = 0; k < IN_DIM; k += 4) {
        float4 a4[8];
#pragma unroll
        for (int i = 0; i < 8; i++)
            a4[i] = *(const float4*)&xs[(mrow + i) * XS_STR + k];
#pragma unroll
        for (int j = 0; j < 8; j++) {
            float4 b4 = *(const float4*)&ws[(mcol + 16 * j) * WS_STR + k];
            // each element's chain: k, k+1, k+2, k+3 (ascending, unchanged)
#pragma unroll
            for (int i = 0; i < 8; i++) {
                acc[i][j] = fmaf(a4[i].x, b4.x, acc[i][j]);
                acc[i][j] = fmaf(a4[i].y, b4.y, acc[i][j]);
                acc[i][j] = fmaf(a4[i].z, b4.z, acc[i][j]);
                acc[i][j] = fmaf(a4[i].w, b4.w, acc[i][j]);
            }
        }
    }

    float* op = g_xw + rowbase * HID;
#pragma unroll
    for (int i = 0; i < 8; i++)
#pragma unroll
        for (int j = 0; j < 8; j++)
            op[(mrow + i) * HID + mcol + 16 * j] = acc[i][j];
}

// ---------------------------------------------------------------------------
// Simulation chunk [t0, t0+CH_STEPS): R2's exact numeric path. State
// round-trips through gmem in exact fp32 bits. SMEM = w_rec only (64 KB).
// ---------------------------------------------------------------------------
#define SIM_SMEM (HID * HID * 4)   // 65,536 B

__global__ __launch_bounds__(256)
void sim_kernel(const float* __restrict__ wout, float* __restrict__ out,
                int t0) {
    extern __shared__ float sm[];
    float* wrp = sm;
    int tid = threadIdx.x, lane = tid & 31, wid = tid >> 5;
    int b = blockIdx.x * 8 + wid;

    {
        const float4* s4 = (const float4*)g_wrp;
        float4* d4 = (float4*)wrp;
        for (int e = tid; e < HID * HID / 4; e += 256) d4[e] = s4[e];
    }
    __syncthreads();

    float v0, v1, v2, v3, i0, i1, i2, i3, a0, a1, a2, a3;
    if (t0 == 0) {
        v0 = v1 = v2 = v3 = 0.f;
        i0 = i1 = i2 = i3 = 0.f;
        a0 = a1 = a2 = a3 = 0.f;
    } else {
        const float* pv = g_v + b * HID;
        const float* pi = g_i + b * HID;
        const float* pa = g_a + b * HID;
        v0 = pv[lane]; v1 = pv[32 + lane]; v2 = pv[64 + lane]; v3 = pv[96 + lane];
        i0 = pi[lane]; i1 = pi[32 + lane]; i2 = pi[64 + lane]; i3 = pi[96 + lane];
        a0 = pa[lane]; a1 = pa[32 + lane]; a2 = pa[64 + lane]; a3 = pa[96 + lane];
    }

    const float* xwp = g_xw + ((size_t)t0 * BATCH + b) * HID + lane;
    const size_t tstride = (size_t)BATCH * HID;
    const float4* wr4 = (const float4*)wrp;

    float xn0 = xwp[0], xn1 = xwp[32], xn2 = xwp[64], xn3 = xwp[96];

    for (int tl = 0; tl < CH_STEPS; ++tl) {
        float xc0 = xn0, xc1 = xn1, xc2 = xn2, xc3 = xn3;
        if (tl + 1 < CH_STEPS) {
            const float* p = xwp + (size_t)(tl + 1) * tstride;
            xn0 = p[0]; xn1 = p[32]; xn2 = p[64]; xn3 = p[96];
        }
        float ct = __ldg(&g_coef[t0 + tl]);

        float vd0 = __fadd_rn(v0, __fmul_rn(0.1f, __fadd_rn(__fsub_rn(0.f, v0), i0)));
        float vd1 = __fadd_rn(v1, __fmul_rn(0.1f, __fadd_rn(__fsub_rn(0.f, v1), i1)));
        float vd2 = __fadd_rn(v2, __fmul_rn(0.1f, __fadd_rn(__fsub_rn(0.f, v2), i2)));
        float vd3 = __fadd_rn(v3, __fmul_rn(0.1f, __fadd_rn(__fsub_rn(0.f, v3), i3)));
        float id0 = __fsub_rn(i0, __fmul_rn(0.2f, i0));
        float id1 = __fsub_rn(i1, __fmul_rn(0.2f, i1));
        float id2 = __fsub_rn(i2, __fmul_rn(0.2f, i2));
        float id3 = __fsub_rn(i3, __fmul_rn(0.2f, i3));
        bool z0 = __fsub_rn(vd0, 1.0f) > 0.0f;
        bool z1 = __fsub_rn(vd1, 1.0f) > 0.0f;
        bool z2 = __fsub_rn(vd2, 1.0f) > 0.0f;
        bool z3 = __fsub_rn(vd3, 1.0f) > 0.0f;
        v0 = z0 ? 0.0f : vd0;
        v1 = z1 ? 0.0f : vd1;
        v2 = z2 ? 0.0f : vd2;
        v3 = z3 ? 0.0f : vd3;
        if (z0) a0 = __fadd_rn(a0, ct);
        if (z1) a1 = __fadd_rn(a1, ct);
        if (z2) a2 = __fadd_rn(a2, ct);
        if (z3) a3 = __fadd_rn(a3, ct);

        unsigned m0 = __ballot_sync(0xffffffffu, z0);
        unsigned m1 = __ballot_sync(0xffffffffu, z1);
        unsigned m2 = __ballot_sync(0xffffffffu, z2);
        unsigned m3 = __ballot_sync(0xffffffffu, z3);
        float R0 = 0.f, R1 = 0.f, R2 = 0.f, R3 = 0.f;
        while (m0) {
            int k = __ffs((int)m0) - 1; m0 &= m0 - 1;
            float4 q = wr4[k * 32 + lane];
            R0 = __fadd_rn(R0, q.x); R1 = __fadd_rn(R1, q.y);
            R2 = __fadd_rn(R2, q.z); R3 = __fadd_rn(R3, q.w);
        }
        while (m1) {
            int k = 32 + __ffs((int)m1) - 1; m1 &= m1 - 1;
            float4 q = wr4[k * 32 + lane];
            R0 = __fadd_rn(R0, q.x); R1 = __fadd_rn(R1, q.y);
            R2 = __fadd_rn(R2, q.z); R3 = __fadd_rn(R3, q.w);
        }
        while (m2) {
            int k = 64 + __ffs((int)m2) - 1; m2 &= m2 - 1;
            float4 q = wr4[k * 32 + lane];
            R0 = __fadd_rn(R0, q.x); R1 = __fadd_rn(R1, q.y);
            R2 = __fadd_rn(R2, q.z); R3 = __fadd_rn(R3, q.w);
        }
        while (m3) {
            int k = 96 + __ffs((int)m3) - 1; m3 &= m3 - 1;
            float4 q = wr4[k * 32 + lane];
            R0 = __fadd_rn(R0, q.x); R1 = __fadd_rn(R1, q.y);
            R2 = __fadd_rn(R2, q.z); R3 = __fadd_rn(R3, q.w);
        }
        i0 = __fadd_rn(__fadd_rn(id0, xc0), R0);
        i1 = __fadd_rn(__fadd_rn(id1, xc1), R1);
        i2 = __fadd_rn(__fadd_rn(id2, xc2), R2);
        i3 = __fadd_rn(__fadd_rn(id3, xc3), R3);
    }

    if (t0 + CH_STEPS < T_STEPS) {
        float* pv = g_v + b * HID;
        float* pi = g_i + b * HID;
        float* pa = g_a + b * HID;
        pv[lane] = v0; pv[32 + lane] = v1; pv[64 + lane] = v2; pv[96 + lane] = v3;
        pi[lane] = i0; pi[32 + lane] = i1; pi[64 + lane] = i2; pi[96 + lane] = i3;
        pa[lane] = a0; pa[32 + lane] = a1; pa[64 + lane] = a2; pa[96 + lane] = a3;
    } else {
        float vo[OUT_DIM];
#pragma unroll
        for (int o = 0; o < OUT_DIM; ++o) {
            const float* wp = wout + o * HID;
            float p = a0 * wp[lane] + a1 * wp[32 + lane] + a2 * wp[64 + lane] +
                      a3 * wp[96 + lane];
#pragma unroll
            for (int s = 16; s; s >>= 1) p += __shfl_xor_sync(0xffffffffu, p, s);
            vo[o] = p;
        }
        if (lane == 0) {
            float mx = vo[0];
#pragma unroll
            for (int o = 1; o < OUT_DIM; ++o) mx = fmaxf(mx, vo[o]);
            float se = 0.f;
#pragma unroll
            for (int o = 0; o < OUT_DIM; ++o) se += expf(vo[o] - mx);
            float lse = mx + logf(se);
#pragma unroll
            for (int o = 0; o < OUT_DIM; ++o) out[b * OUT_DIM + o] = vo[o] - lse;
        }
    }
}

extern "C" void kernel_launch(void* const* d_in, const int* in_sizes, int n_in,
                              void* d_out, int out_size) {
    const float* x     = (const float*)d_in[0];
    const float* w_in  = (const float*)d_in[1];
    const float* w_rec = (const float*)d_in[2];
    const float* w_out = (const float*)d_in[3];
    float* out = (float*)d_out;

    cudaFuncSetAttribute(gemm_in, cudaFuncAttributeMaxDynamicSharedMemorySize,
                         GEMM_SMEM);
    cudaFuncSetAttribute(sim_kernel, cudaFuncAttributeMaxDynamicSharedMemorySize,
                         SIM_SMEM);

    // GEMM pipeline on a low-priority forked stream; sim chunks on stream 0.
    int prLo = 0, prHi = 0;
    cudaDeviceGetStreamPriorityRange(&prLo, &prHi);
    cudaStream_t s1;
    cudaStreamCreateWithPriority(&s1, cudaStreamNonBlocking, prLo);
    cudaEvent_t evF;
    cudaEventCreateWithFlags(&evF, cudaEventDisableTiming);
    cudaEvent_t evg[CHUNKS];
    for (int c = 0; c < CHUNKS; ++c)
        cudaEventCreateWithFlags(&evg[c], cudaEventDisableTiming);

    cudaEventRecord(evF, 0);
    cudaStreamWaitEvent(s1, evF, 0);

    prep_kernel<<<64, 256, 0, 0>>>(w_rec);

    for (int c = 0; c < CHUNKS; ++c) {
        gemm_in<<<TILES_PER_CHUNK, 256, GEMM_SMEM, s1>>>(
            x, w_in, c * TILES_PER_CHUNK);
        cudaEventRecord(evg[c], s1);
    }
    for (int c = 0; c < CHUNKS; ++c) {
        cudaStreamWaitEvent(0, evg[c], 0);
        sim_kernel<<<BATCH / 8, 256, SIM_SMEM, 0>>>(w_out, out, c * CH_STEPS);
    }
}